// round 12
// baseline (speedup 1.0000x reference)
#include <cuda_runtime.h>
#include <cuda_fp16.h>
#include <math.h>
#include <stdint.h>

// Shapes (fixed)
#define R_TOTAL 4096
#define DQ      512
#define DC      256
#define MTOK    64
#define NHEADS  8
#define DHEAD   64
#define INNER   512

// Scratch (no allocs allowed) — fp16 everywhere
__device__ __half g_xh  [R_TOTAL * DQ];             // 4 MB
__device__ __half g_Qh  [R_TOTAL * INNER];          // 4 MB
__device__ __half g_Qkh [R_TOTAL * NHEADS * DC];    // 16 MB
__device__ __half g_ctxAh[R_TOTAL * NHEADS * DC];   // 16 MB
__device__ __half g_O1h [R_TOTAL * INNER];          // 4 MB
__device__ __half g_WqTh[INNER * DQ];
__device__ __half g_WoTh[DQ * INNER];
__device__ __half g_WvTh[INNER * DC];
__device__ __half g_Wkh [DC * INNER];

// ---------------- helpers ----------------
__device__ __forceinline__ uint32_t smem_u32(const void* p) {
    uint32_t a;
    asm("{ .reg .u64 t; cvta.to.shared.u64 t, %1; cvt.u32.u64 %0, t; }"
        : "=r"(a) : "l"(p));
    return a;
}
__device__ __forceinline__ void ldm_x4(uint32_t* r, uint32_t addr) {
    asm volatile("ldmatrix.sync.aligned.m8n8.x4.shared.b16 {%0,%1,%2,%3}, [%4];"
                 : "=r"(r[0]), "=r"(r[1]), "=r"(r[2]), "=r"(r[3]) : "r"(addr));
}
__device__ __forceinline__ void ldm_x2(uint32_t* r, uint32_t addr) {
    asm volatile("ldmatrix.sync.aligned.m8n8.x2.shared.b16 {%0,%1}, [%2];"
                 : "=r"(r[0]), "=r"(r[1]) : "r"(addr));
}
__device__ __forceinline__ void ldm_x4_t(uint32_t* r, uint32_t addr) {
    asm volatile("ldmatrix.sync.aligned.m8n8.x4.trans.shared.b16 {%0,%1,%2,%3}, [%4];"
                 : "=r"(r[0]), "=r"(r[1]), "=r"(r[2]), "=r"(r[3]) : "r"(addr));
}
__device__ __forceinline__ void ldm_x2_t(uint32_t* r, uint32_t addr) {
    asm volatile("ldmatrix.sync.aligned.m8n8.x2.trans.shared.b16 {%0,%1}, [%2];"
                 : "=r"(r[0]), "=r"(r[1]) : "r"(addr));
}
__device__ __forceinline__ void mma_f16(float* c, const uint32_t* a, const uint32_t* b) {
    asm volatile("mma.sync.aligned.m16n8k16.row.col.f32.f16.f16.f32 "
                 "{%0,%1,%2,%3}, {%4,%5,%6,%7}, {%8,%9}, {%0,%1,%2,%3};"
                 : "+f"(c[0]), "+f"(c[1]), "+f"(c[2]), "+f"(c[3])
                 : "r"(a[0]), "r"(a[1]), "r"(a[2]), "r"(a[3]), "r"(b[0]), "r"(b[1]));
}
__device__ __forceinline__ uint2 pack_h(float4 v) {
    __half2 h01 = __float22half2_rn(make_float2(v.x, v.y));
    __half2 h23 = __float22half2_rn(make_float2(v.z, v.w));
    return make_uint2(*(uint32_t*)&h01, *(uint32_t*)&h23);
}

// ---------------------------------------------------------------------------
// One-shot converters (bit-identical to the previous per-tile pack_h rounding)
// ---------------------------------------------------------------------------
__global__ void tohalf_k(const float* __restrict__ src, __half* __restrict__ dst)
{
    int i = (blockIdx.x * 256 + threadIdx.x) * 4;
    float4 v = *(const float4*)(src + i);
    *(uint2*)(dst + i) = pack_h(v);
}

__global__ void transpose_kh(const float* __restrict__ src, __half* __restrict__ dst,
                             int R, int C)
{
    __shared__ float tile[32][33];
    int bx = blockIdx.x * 32, by = blockIdx.y * 32;
#pragma unroll
    for (int j = 0; j < 32; j += 8)
        tile[threadIdx.y + j][threadIdx.x] =
            src[(long long)(by + threadIdx.y + j) * C + bx + threadIdx.x];
    __syncthreads();
#pragma unroll
    for (int j = 0; j < 32; j += 8)
        dst[(long long)(bx + threadIdx.y + j) * R + by + threadIdx.x] =
            __float2half_rn(tile[threadIdx.x][threadIdx.y + j]);
}

// ---------------------------------------------------------------------------
// All-fp16 single-term mma.sync GEMM: C = A·B^T (+bias), A,B fp16 in gmem.
// HOUT: write C as fp16 else fp32.
// ---------------------------------------------------------------------------
#define LROW 40
#define LROWB 80

template<int BM, int BN, int MW, int NW, bool BIAS, bool HOUT>
__global__ __launch_bounds__(256, 3)
void hgemm(const __half* __restrict__ A, int lda, long long bsA,
           const __half* __restrict__ B, int ldb, long long bsB,
           void* __restrict__ Cv, int ldc, long long bsC,
           const float* __restrict__ bias, int K)
{
    constexpr int WM = BM / MW;
    constexpr int WN = BN / NW;
    constexpr int MT = WM / 16;
    constexpr int NT = WN / 8;
    constexpr int A_BYTES = BM * LROWB;
    constexpr int B_BYTES = BN * LROWB;
    constexpr int STAGE = A_BYTES + B_BYTES;

    extern __shared__ char smc[];
    const uint32_t smb = smem_u32(smc);

    const int t = threadIdx.x;
    const int wid = t >> 5, lane = t & 31;
    const int wr = wid / NW, wc = wid % NW;
    const int wm = wr * WM, wn = wc * WN;
    const int bm = blockIdx.y * BM, bn = blockIdx.x * BN;

    A += (long long)blockIdx.z * bsA;
    B += (long long)blockIdx.z * bsB;

    const int rr  = t >> 2;        // 0..63 (row)
    const int c16 = t & 3;         // 16B column group (8 halves)

    float acc[MT][NT][4];
#pragma unroll
    for (int i = 0; i < MT; i++)
#pragma unroll
        for (int j = 0; j < NT; j++)
#pragma unroll
            for (int q = 0; q < 4; q++) acc[i][j][q] = 0.0f;

    const int ns = K >> 5;
    uint4 pa[BM / 64], pb[BN / 64];

    const uint32_t a_off = (uint32_t)(((wm + (lane & 15)) * LROW + (lane >> 4) * 8) * 2);
    const uint32_t b_off = (uint32_t)(((wn + (lane & 7)) * LROW + ((lane >> 3) & 1) * 8) * 2);

    auto gload = [&](int s) {
#pragma unroll
        for (int i = 0; i < BM / 64; i++)
            pa[i] = *(const uint4*)(A + (long long)(bm + rr + i * 64) * lda + s * 32 + c16 * 8);
#pragma unroll
        for (int i = 0; i < BN / 64; i++)
            pb[i] = *(const uint4*)(B + (long long)(bn + rr + i * 64) * ldb + s * 32 + c16 * 8);
    };
    auto sstore = [&](int buf) {
        char* base = smc + buf * STAGE;
#pragma unroll
        for (int i = 0; i < BM / 64; i++)
            *(uint4*)(base + (rr + i * 64) * LROWB + c16 * 16) = pa[i];
        char* bb = base + A_BYTES;
#pragma unroll
        for (int i = 0; i < BN / 64; i++)
            *(uint4*)(bb + (rr + i * 64) * LROWB + c16 * 16) = pb[i];
    };
    auto compute = [&](int buf) {
        const uint32_t sa = smb + buf * STAGE;
        const uint32_t sb = sa + A_BYTES;
#pragma unroll
        for (int ks = 0; ks < 2; ks++) {
            uint32_t afh[MT][4], bfh[NT][2];
#pragma unroll
            for (int mt = 0; mt < MT; mt++)
                ldm_x4(afh[mt], sa + a_off + mt * (16 * LROWB) + ks * 32);
#pragma unroll
            for (int nt = 0; nt < NT; nt++)
                ldm_x2(bfh[nt], sb + b_off + nt * (8 * LROWB) + ks * 32);
#pragma unroll
            for (int mt = 0; mt < MT; mt++)
#pragma unroll
                for (int nt = 0; nt < NT; nt++)
                    mma_f16(acc[mt][nt], afh[mt], bfh[nt]);
        }
    };

    gload(0);
    sstore(0);
    __syncthreads();
    for (int s = 0; s < ns; s++) {
        if (s + 1 < ns) gload(s + 1);
        compute(s & 1);
        if (s + 1 < ns) {
            sstore((s + 1) & 1);
            __syncthreads();
        }
    }

    const int g = lane >> 2, tq = lane & 3;
    if (HOUT) {
        __half* C = (__half*)Cv + (long long)blockIdx.z * bsC;
#pragma unroll
        for (int mt = 0; mt < MT; mt++) {
            int r0 = bm + wm + mt * 16 + g;
#pragma unroll
            for (int nt = 0; nt < NT; nt++) {
                int col = bn + wn + nt * 8 + tq * 2;
                __half2 v0 = __float22half2_rn(make_float2(acc[mt][nt][0], acc[mt][nt][1]));
                __half2 v1 = __float22half2_rn(make_float2(acc[mt][nt][2], acc[mt][nt][3]));
                *(__half2*)(C + (long long)r0 * ldc + col)       = v0;
                *(__half2*)(C + (long long)(r0 + 8) * ldc + col) = v1;
            }
        }
    } else {
        float* C = (float*)Cv + (long long)blockIdx.z * bsC;
#pragma unroll
        for (int mt = 0; mt < MT; mt++) {
            int r0 = bm + wm + mt * 16 + g;
#pragma unroll
            for (int nt = 0; nt < NT; nt++) {
                int col = bn + wn + nt * 8 + tq * 2;
                float b0 = 0.f, b1 = 0.f;
                if (BIAS) { b0 = bias[col]; b1 = bias[col + 1]; }
                *(float2*)(C + (long long)r0 * ldc + col) =
                    make_float2(acc[mt][nt][0] + b0, acc[mt][nt][1] + b1);
                *(float2*)(C + (long long)(r0 + 8) * ldc + col) =
                    make_float2(acc[mt][nt][2] + b0, acc[mt][nt][3] + b1);
            }
        }
    }
}

// ---------------------------------------------------------------------------
// Tensor-core attention core, single-term fp16 (unchanged from round 10).
// ---------------------------------------------------------------------------
#define AC_LDC 528
#define AC_CH 0
#define AC_QH 33792
#define AC_AH 38016
#define AC_SA 41088
#define AC_SB 43392
#define AC_BI 45696
#define AC_MK 45952
#define AC_BYTES 46208

__global__ __launch_bounds__(256)
void attn_core(const float* __restrict__ ctx,
               const int* __restrict__ mask,
               const float* __restrict__ bias)
{
    extern __shared__ char sm[];
    const uint32_t smb = smem_u32(sm);
    const int r = blockIdx.x, t = threadIdx.x;
    const int wid = t >> 5, lane = t & 31;

    {
        const float4* g = (const float4*)(ctx + (size_t)r * (MTOK * DC));
#pragma unroll
        for (int s = 0; s < 16; s++) {
            int i = t + s * 256;
            int m = i >> 6, c4 = i & 63;
            *(uint2*)(sm + AC_CH + m * AC_LDC + c4 * 8) = pack_h(g[i]);
        }
        {
            const uint4* gq = (const uint4*)(g_Qkh + (size_t)r * (NHEADS * DC));
            uint4 v = gq[t];
            int h = t >> 5, c16 = t & 31;
            *(uint4*)(sm + AC_QH + h * AC_LDC + c16 * 16) = v;
        }
        if (t < MTOK) {
            ((float*)(sm + AC_BI))[t] = bias[(size_t)r * MTOK + t];
            ((int*)(sm + AC_MK))[t]   = mask[(size_t)r * MTOK + t];
        }
    }
    __syncthreads();

    {
        const int mtile = wid & 3, khalf = wid >> 2;
        float d[4] = {0.f, 0.f, 0.f, 0.f};
        const uint32_t a_base = smb + AC_CH +
            (uint32_t)((mtile * 16 + (lane & 15)) * AC_LDC + (lane >> 4) * 16);
        const uint32_t b_base = smb + AC_QH +
            (uint32_t)((lane & 7) * AC_LDC + ((lane >> 3) & 1) * 16);
#pragma unroll
        for (int j = 0; j < 8; j++) {
            const int kk = khalf * 8 + j;
            uint32_t ah[4], bh[2];
            ldm_x4(ah, a_base + kk * 32);
            ldm_x2(bh, b_base + kk * 32);
            mma_f16(d, ah, bh);
        }
        float* ss = (float*)(sm + (khalf ? AC_SB : AC_SA));
        const int gg = lane >> 2, tq = lane & 3;
        const int m0 = mtile * 16 + gg;
        ss[m0 * 9 + 2 * tq]           = d[0];
        ss[m0 * 9 + 2 * tq + 1]       = d[1];
        ss[(m0 + 8) * 9 + 2 * tq]     = d[2];
        ss[(m0 + 8) * 9 + 2 * tq + 1] = d[3];
    }
    __syncthreads();

    {
        const int w = wid;
        const float* sa = (const float*)(sm + AC_SA);
        const float* sb = (const float*)(sm + AC_SB);
        const float* sbias = (const float*)(sm + AC_BI);
        const int*   smask = (const int*)(sm + AC_MK);
        const int m0 = lane, m1 = lane + 32;
        float v0 = (sa[m0 * 9 + w] + sb[m0 * 9 + w]) * 0.125f + sbias[m0];
        float v1 = (sa[m1 * 9 + w] + sb[m1 * 9 + w]) * 0.125f + sbias[m1];
        if (!smask[m0]) v0 = -INFINITY;
        if (!smask[m1]) v1 = -INFINITY;
        float mx = fmaxf(v0, v1);
#pragma unroll
        for (int o = 16; o; o >>= 1) mx = fmaxf(mx, __shfl_xor_sync(0xffffffffu, mx, o));
        float e0 = __expf(v0 - mx);
        float e1 = __expf(v1 - mx);
        float s = e0 + e1;
#pragma unroll
        for (int o = 16; o; o >>= 1) s += __shfl_xor_sync(0xffffffffu, s, o);
        float inv = 1.0f / s;
        __half h0 = __float2half_rn(e0 * inv);
        __half h1 = __float2half_rn(e1 * inv);
        uint16_t* ah = (uint16_t*)(sm + AC_AH);
        ah[m0 * 24 + w] = *(uint16_t*)&h0;
        ah[m1 * 24 + w] = *(uint16_t*)&h1;
    }
    __syncthreads();

    {
        float d0[4] = {0.f, 0.f, 0.f, 0.f};
        float d1[4] = {0.f, 0.f, 0.f, 0.f};
        const int c0 = wid * 32;
        const uint32_t bt_base = smb + AC_AH +
            (uint32_t)((((lane >> 3) & 1) * 8 + (lane & 7)) * 48);
        const uint32_t at_row = (uint32_t)(((lane >> 4) & 1) * 8 + (lane & 7));
        const uint32_t at_col = (uint32_t)(((lane >> 3) & 1) * 16);
#pragma unroll
        for (int kk = 0; kk < 4; kk++) {
            uint32_t bh[2];
            ldm_x2_t(bh, bt_base + kk * 16 * 48);
            const uint32_t arow = smb + AC_CH + (kk * 16 + at_row) * AC_LDC + at_col;
            uint32_t ah0[4], ah1[4];
            ldm_x4_t(ah0, arow + c0 * 2);
            ldm_x4_t(ah1, arow + (c0 + 16) * 2);
            mma_f16(d0, ah0, bh);
            mma_f16(d1, ah1, bh);
        }
        const int gg = lane >> 2, tq = lane & 3;
        __half* o = g_ctxAh + (size_t)r * (NHEADS * DC);
        int c = c0 + gg;
        o[(2 * tq) * DC + c]         = __float2half_rn(d0[0]);
        o[(2 * tq + 1) * DC + c]     = __float2half_rn(d0[1]);
        o[(2 * tq) * DC + c + 8]     = __float2half_rn(d0[2]);
        o[(2 * tq + 1) * DC + c + 8] = __float2half_rn(d0[3]);
        c = c0 + 16 + gg;
        o[(2 * tq) * DC + c]         = __float2half_rn(d1[0]);
        o[(2 * tq + 1) * DC + c]     = __float2half_rn(d1[1]);
        o[(2 * tq) * DC + c + 8]     = __float2half_rn(d1[2]);
        o[(2 * tq + 1) * DC + c + 8] = __float2half_rn(d1[3]);
    }
}

// ---------------------------------------------------------------------------
extern "C" void kernel_launch(void* const* d_in, const int* in_sizes, int n_in,
                              void* d_out, int out_size)
{
    const float* x    = (const float*)d_in[0];
    const float* ctx  = (const float*)d_in[1];
    const int*   mask = (const int*)d_in[2];
    const float* bias = (const float*)d_in[3];
    const float* Wq   = (const float*)d_in[4];
    const float* Wk   = (const float*)d_in[5];
    const float* Wv   = (const float*)d_in[6];
    const float* Wo   = (const float*)d_in[7];
    const float* bo   = (const float*)d_in[8];
    float*       out  = (float*)d_out;

    __half *xhp, *Qhp, *Qkhp, *cAhp, *O1hp, *WqThp, *WoThp, *WvThp, *Wkhp;
    cudaGetSymbolAddress((void**)&xhp,   g_xh);
    cudaGetSymbolAddress((void**)&Qhp,   g_Qh);
    cudaGetSymbolAddress((void**)&Qkhp,  g_Qkh);
    cudaGetSymbolAddress((void**)&cAhp,  g_ctxAh);
    cudaGetSymbolAddress((void**)&O1hp,  g_O1h);
    cudaGetSymbolAddress((void**)&WqThp, g_WqTh);
    cudaGetSymbolAddress((void**)&WoThp, g_WoTh);
    cudaGetSymbolAddress((void**)&WvThp, g_WvTh);
    cudaGetSymbolAddress((void**)&Wkhp,  g_Wkh);

    const int SM_64_128 = 2 * (64 * LROWB + 128 * LROWB);   // 30720
    const int SM_64_64  = 2 * (64 * LROWB + 64 * LROWB);    // 20480
    cudaFuncSetAttribute((const void*)hgemm<64, 128, 2, 4, false, true>,
                         cudaFuncAttributeMaxDynamicSharedMemorySize, SM_64_128);
    cudaFuncSetAttribute((const void*)hgemm<64, 128, 2, 4, true,  false>,
                         cudaFuncAttributeMaxDynamicSharedMemorySize, SM_64_128);
    cudaFuncSetAttribute((const void*)hgemm<64, 64, 2, 4, false, true>,
                         cudaFuncAttributeMaxDynamicSharedMemorySize, SM_64_64);
    cudaFuncSetAttribute((const void*)attn_core,
                         cudaFuncAttributeMaxDynamicSharedMemorySize, AC_BYTES);

    // one-shot converts (cheap; replayed each graph launch, still cheap)
    tohalf_k<<<(R_TOTAL * DQ) / 1024, 256>>>(x, xhp);
    tohalf_k<<<(DC * INNER) / 1024, 256>>>(Wk, Wkhp);
    dim3 tb(32, 8);
    transpose_kh<<<dim3(16, 16), tb>>>(Wq, WqThp, DQ, INNER);
    transpose_kh<<<dim3(16, 16), tb>>>(Wo, WoThp, INNER, DQ);
    transpose_kh<<<dim3(16, 8),  tb>>>(Wv, WvThp, DC, INNER);

    // K1: Q = xh @ WqTh^T -> fp16 Q
    hgemm<64, 128, 2, 4, false, true><<<dim3(INNER / 128, R_TOTAL / 64, 1), 256, SM_64_128>>>(
        xhp, DQ, 0, WqThp, DQ, 0, Qhp, INNER, 0, nullptr, DQ);

    // K2: Qk = Qh @ Wkh^T (per head) -> fp16 Qk
    hgemm<64, 128, 2, 4, false, true><<<dim3(DC / 128, R_TOTAL / 64, NHEADS), 256, SM_64_128>>>(
        Qhp, INNER, DHEAD, Wkhp, INNER, DHEAD, Qkhp, NHEADS * DC, DC, nullptr, DHEAD);

    // K3: fused attention core -> fp16 ctxA
    attn_core<<<R_TOTAL, 256, AC_BYTES>>>(ctx, mask, bias);

    // K4: O1 = ctxAh @ WvTh^T (per head) -> fp16 O1
    hgemm<64, 64, 2, 4, false, true><<<dim3(1, R_TOTAL / 64, NHEADS), 256, SM_64_64>>>(
        cAhp, NHEADS * DC, DC, WvThp, DC, (long long)DHEAD * DC,
        O1hp, INNER, DHEAD, nullptr, DC);

    // K5: out = O1h @ WoTh^T + bo (fp32 out)
    hgemm<64, 128, 2, 4, true, false><<<dim3(DQ / 128, R_TOTAL / 64, 1), 256, SM_64_128>>>(
        O1hp, INNER, 0, WoThp, INNER, 0, out, DQ, 0, bo, INNER);
}

// round 16
// speedup vs baseline: 1.0576x; 1.0576x over previous
#include <cuda_runtime.h>
#include <cuda_fp16.h>
#include <math.h>
#include <stdint.h>

// Shapes (fixed)
#define R_TOTAL 4096
#define DQ      512
#define DC      256
#define MTOK    64
#define NHEADS  8
#define DHEAD   64
#define INNER   512

// Scratch (no allocs allowed)
__device__ __half g_Qh   [R_TOTAL * INNER];          // 4 MB
__device__ __half g_Qkh  [R_TOTAL * NHEADS * DC];    // 16 MB
__device__ __half g_ctxAh[R_TOTAL * NHEADS * DC];    // 16 MB
__device__ __half g_O1h  [R_TOTAL * INNER];          // 4 MB

// ---------------- helpers ----------------
__device__ __forceinline__ uint32_t smem_u32(const void* p) {
    uint32_t a;
    asm("{ .reg .u64 t; cvta.to.shared.u64 t, %1; cvt.u32.u64 %0, t; }"
        : "=r"(a) : "l"(p));
    return a;
}
__device__ __forceinline__ void ldm_x4(uint32_t* r, uint32_t addr) {
    asm volatile("ldmatrix.sync.aligned.m8n8.x4.shared.b16 {%0,%1,%2,%3}, [%4];"
                 : "=r"(r[0]), "=r"(r[1]), "=r"(r[2]), "=r"(r[3]) : "r"(addr));
}
__device__ __forceinline__ void ldm_x2(uint32_t* r, uint32_t addr) {
    asm volatile("ldmatrix.sync.aligned.m8n8.x2.shared.b16 {%0,%1}, [%2];"
                 : "=r"(r[0]), "=r"(r[1]) : "r"(addr));
}
__device__ __forceinline__ void ldm_x4_t(uint32_t* r, uint32_t addr) {
    asm volatile("ldmatrix.sync.aligned.m8n8.x4.trans.shared.b16 {%0,%1,%2,%3}, [%4];"
                 : "=r"(r[0]), "=r"(r[1]), "=r"(r[2]), "=r"(r[3]) : "r"(addr));
}
__device__ __forceinline__ void ldm_x2_t(uint32_t* r, uint32_t addr) {
    asm volatile("ldmatrix.sync.aligned.m8n8.x2.trans.shared.b16 {%0,%1}, [%2];"
                 : "=r"(r[0]), "=r"(r[1]) : "r"(addr));
}
__device__ __forceinline__ void mma_f16(float* c, const uint32_t* a, const uint32_t* b) {
    asm volatile("mma.sync.aligned.m16n8k16.row.col.f32.f16.f16.f32 "
                 "{%0,%1,%2,%3}, {%4,%5,%6,%7}, {%8,%9}, {%0,%1,%2,%3};"
                 : "+f"(c[0]), "+f"(c[1]), "+f"(c[2]), "+f"(c[3])
                 : "r"(a[0]), "r"(a[1]), "r"(a[2]), "r"(a[3]), "r"(b[0]), "r"(b[1]));
}
__device__ __forceinline__ uint2 pack_h(float4 v) {
    __half2 h01 = __float22half2_rn(make_float2(v.x, v.y));
    __half2 h23 = __float22half2_rn(make_float2(v.z, v.w));
    return make_uint2(*(uint32_t*)&h01, *(uint32_t*)&h23);
}

// ---------------------------------------------------------------------------
// All-tensor fp16 single-term GEMM: C[m][n] = sum_k A[m][k]*B(k,n) (+bias[n]).
// AHALF: A fp16 [m][k] in gmem, else fp32 [m][k] (packed per tile).
// BMODE==1: B fp32 [n][k] (k contiguous)  -> normal ldmatrix
// BMODE==2: B fp32 [k][n] (n contiguous)  -> k-major smem tile + ldmatrix.trans
// HOUT: write C fp16 else fp32.
// ---------------------------------------------------------------------------
#define LROW 40
#define LROWB 80

template<int BM, int BN, int MW, int NW, bool BIAS, bool HOUT, bool AHALF, int BMODE>
__global__ __launch_bounds__(256, 3)
void hgemm(const void* __restrict__ Av, int lda, long long bsA,
           const float* __restrict__ B, int ldb, long long bsB,
           void* __restrict__ Cv, int ldc, long long bsC,
           const float* __restrict__ bias, int K)
{
    constexpr int WM = BM / MW;
    constexpr int WN = BN / NW;
    constexpr int MT = WM / 16;
    constexpr int NT = WN / 8;
    constexpr int A_BYTES = BM * LROWB;
    constexpr int BROWB   = (BMODE == 2) ? (BN * 2 + 16) : LROWB;   // bytes/row
    constexpr int B_BYTES = (BMODE == 2) ? (32 * BROWB) : (BN * LROWB);
    constexpr int STAGE = A_BYTES + B_BYTES;

    extern __shared__ char smc[];
    const uint32_t smb = smem_u32(smc);

    const int t = threadIdx.x;
    const int wid = t >> 5, lane = t & 31;
    const int wr = wid / NW, wc = wid % NW;
    const int wm = wr * WM, wn = wc * WN;
    const int bm = blockIdx.y * BM, bn = blockIdx.x * BN;

    const float*  Af = AHALF ? nullptr : ((const float*)Av + (long long)blockIdx.z * bsA);
    const __half* Ah = AHALF ? ((const __half*)Av + (long long)blockIdx.z * bsA) : nullptr;
    B += (long long)blockIdx.z * bsB;

    float acc[MT][NT][4];
#pragma unroll
    for (int i = 0; i < MT; i++)
#pragma unroll
        for (int j = 0; j < NT; j++)
#pragma unroll
            for (int q = 0; q < 4; q++) acc[i][j][q] = 0.0f;

    const int ns = K >> 5;

    // A staging regs
    uint4  pah[BM / 64];
    float4 paf[BM / 32];
    // B staging regs
    constexpr int CPR   = BN / 4;          // float4 per row (mode2)
    constexpr int RPI   = 256 / CPR;       // rows per iter  (mode2)
    constexpr int IT2   = 32 / RPI;        // iters          (mode2)
    float4 pbt[(BMODE == 2) ? IT2 : (BN / 32)];

    const uint32_t a_off = (uint32_t)(((wm + (lane & 15)) * LROW + (lane >> 4) * 8) * 2);
    const uint32_t b_off1 = (uint32_t)(((wn + (lane & 7)) * LROW + ((lane >> 3) & 1) * 8) * 2);
    const uint32_t b_off2 = (uint32_t)(((((lane >> 3) & 1) * 8 + (lane & 7)) * BROWB) + wn * 2);

    auto gload = [&](int s) {
        if (AHALF) {
#pragma unroll
            for (int i = 0; i < BM / 64; i++)
                pah[i] = *(const uint4*)(Ah + (long long)(bm + (t >> 2) + i * 64) * lda + s * 32 + (t & 3) * 8);
        } else {
#pragma unroll
            for (int i = 0; i < BM / 32; i++)
                paf[i] = *(const float4*)(Af + (long long)(bm + (t >> 3) + i * 32) * lda + s * 32 + (t & 7) * 4);
        }
        if (BMODE == 1) {
#pragma unroll
            for (int i = 0; i < BN / 32; i++)
                pbt[i] = *(const float4*)(B + (long long)(bn + (t >> 3) + i * 32) * ldb + s * 32 + (t & 7) * 4);
        } else {
#pragma unroll
            for (int i = 0; i < IT2; i++)
                pbt[i] = *(const float4*)(B + (long long)(s * 32 + (t / CPR) + i * RPI) * ldb + bn + (t % CPR) * 4);
        }
    };
    auto sstore = [&](int buf) {
        char* base = smc + buf * STAGE;
        if (AHALF) {
#pragma unroll
            for (int i = 0; i < BM / 64; i++)
                *(uint4*)(base + ((t >> 2) + i * 64) * LROWB + (t & 3) * 16) = pah[i];
        } else {
#pragma unroll
            for (int i = 0; i < BM / 32; i++)
                *(uint2*)(base + ((t >> 3) + i * 32) * LROWB + (t & 7) * 8) = pack_h(paf[i]);
        }
        char* bb = base + A_BYTES;
        if (BMODE == 1) {
#pragma unroll
            for (int i = 0; i < BN / 32; i++)
                *(uint2*)(bb + ((t >> 3) + i * 32) * LROWB + (t & 7) * 8) = pack_h(pbt[i]);
        } else {
#pragma unroll
            for (int i = 0; i < IT2; i++)
                *(uint2*)(bb + ((t / CPR) + i * RPI) * BROWB + (t % CPR) * 8) = pack_h(pbt[i]);
        }
    };
    auto compute = [&](int buf) {
        const uint32_t sa = smb + buf * STAGE;
        const uint32_t sb = sa + A_BYTES;
#pragma unroll
        for (int ks = 0; ks < 2; ks++) {
            uint32_t afh[MT][4], bfh[NT][2];
#pragma unroll
            for (int mt = 0; mt < MT; mt++)
                ldm_x4(afh[mt], sa + a_off + mt * (16 * LROWB) + ks * 32);
#pragma unroll
            for (int nt = 0; nt < NT; nt++) {
                if (BMODE == 1)
                    ldm_x2(bfh[nt], sb + b_off1 + nt * (8 * LROWB) + ks * 32);
                else
                    ldm_x2_t(bfh[nt], sb + b_off2 + nt * 16 + ks * (16 * BROWB));
            }
#pragma unroll
            for (int mt = 0; mt < MT; mt++)
#pragma unroll
                for (int nt = 0; nt < NT; nt++)
                    mma_f16(acc[mt][nt], afh[mt], bfh[nt]);
        }
    };

    gload(0);
    sstore(0);
    __syncthreads();
    for (int s = 0; s < ns; s++) {
        if (s + 1 < ns) gload(s + 1);
        compute(s & 1);
        if (s + 1 < ns) {
            sstore((s + 1) & 1);
            __syncthreads();
        }
    }

    const int g = lane >> 2, tq = lane & 3;
    if (HOUT) {
        __half* C = (__half*)Cv + (long long)blockIdx.z * bsC;
#pragma unroll
        for (int mt = 0; mt < MT; mt++) {
            int r0 = bm + wm + mt * 16 + g;
#pragma unroll
            for (int nt = 0; nt < NT; nt++) {
                int col = bn + wn + nt * 8 + tq * 2;
                __half2 v0 = __float22half2_rn(make_float2(acc[mt][nt][0], acc[mt][nt][1]));
                __half2 v1 = __float22half2_rn(make_float2(acc[mt][nt][2], acc[mt][nt][3]));
                *(__half2*)(C + (long long)r0 * ldc + col)       = v0;
                *(__half2*)(C + (long long)(r0 + 8) * ldc + col) = v1;
            }
        }
    } else {
        float* C = (float*)Cv + (long long)blockIdx.z * bsC;
#pragma unroll
        for (int mt = 0; mt < MT; mt++) {
            int r0 = bm + wm + mt * 16 + g;
#pragma unroll
            for (int nt = 0; nt < NT; nt++) {
                int col = bn + wn + nt * 8 + tq * 2;
                float b0 = 0.f, b1 = 0.f;
                if (BIAS) { b0 = bias[col]; b1 = bias[col + 1]; }
                *(float2*)(C + (long long)r0 * ldc + col) =
                    make_float2(acc[mt][nt][0] + b0, acc[mt][nt][1] + b1);
                *(float2*)(C + (long long)(r0 + 8) * ldc + col) =
                    make_float2(acc[mt][nt][2] + b0, acc[mt][nt][3] + b1);
            }
        }
    }
}

// ---------------------------------------------------------------------------
// Tensor-core attention core, single-term fp16 (unchanged, proven).
// ---------------------------------------------------------------------------
#define AC_LDC 528
#define AC_CH 0
#define AC_QH 33792
#define AC_AH 38016
#define AC_SA 41088
#define AC_SB 43392
#define AC_BI 45696
#define AC_MK 45952
#define AC_BYTES 46208

__global__ __launch_bounds__(256)
void attn_core(const float* __restrict__ ctx,
               const int* __restrict__ mask,
               const float* __restrict__ bias)
{
    extern __shared__ char sm[];
    const uint32_t smb = smem_u32(sm);
    const int r = blockIdx.x, t = threadIdx.x;
    const int wid = t >> 5, lane = t & 31;

    {
        const float4* g = (const float4*)(ctx + (size_t)r * (MTOK * DC));
#pragma unroll
        for (int s = 0; s < 16; s++) {
            int i = t + s * 256;
            int m = i >> 6, c4 = i & 63;
            *(uint2*)(sm + AC_CH + m * AC_LDC + c4 * 8) = pack_h(g[i]);
        }
        {
            const uint4* gq = (const uint4*)(g_Qkh + (size_t)r * (NHEADS * DC));
            uint4 v = gq[t];
            int h = t >> 5, c16 = t & 31;
            *(uint4*)(sm + AC_QH + h * AC_LDC + c16 * 16) = v;
        }
        if (t < MTOK) {
            ((float*)(sm + AC_BI))[t] = bias[(size_t)r * MTOK + t];
            ((int*)(sm + AC_MK))[t]   = mask[(size_t)r * MTOK + t];
        }
    }
    __syncthreads();

    {
        const int mtile = wid & 3, khalf = wid >> 2;
        float d[4] = {0.f, 0.f, 0.f, 0.f};
        const uint32_t a_base = smb + AC_CH +
            (uint32_t)((mtile * 16 + (lane & 15)) * AC_LDC + (lane >> 4) * 16);
        const uint32_t b_base = smb + AC_QH +
            (uint32_t)((lane & 7) * AC_LDC + ((lane >> 3) & 1) * 16);
#pragma unroll
        for (int j = 0; j < 8; j++) {
            const int kk = khalf * 8 + j;
            uint32_t ah[4], bh[2];
            ldm_x4(ah, a_base + kk * 32);
            ldm_x2(bh, b_base + kk * 32);
            mma_f16(d, ah, bh);
        }
        float* ss = (float*)(sm + (khalf ? AC_SB : AC_SA));
        const int gg = lane >> 2, tq = lane & 3;
        const int m0 = mtile * 16 + gg;
        ss[m0 * 9 + 2 * tq]           = d[0];
        ss[m0 * 9 + 2 * tq + 1]       = d[1];
        ss[(m0 + 8) * 9 + 2 * tq]     = d[2];
        ss[(m0 + 8) * 9 + 2 * tq + 1] = d[3];
    }
    __syncthreads();

    {
        const int w = wid;
        const float* sa = (const float*)(sm + AC_SA);
        const float* sb = (const float*)(sm + AC_SB);
        const float* sbias = (const float*)(sm + AC_BI);
        const int*   smask = (const int*)(sm + AC_MK);
        const int m0 = lane, m1 = lane + 32;
        float v0 = (sa[m0 * 9 + w] + sb[m0 * 9 + w]) * 0.125f + sbias[m0];
        float v1 = (sa[m1 * 9 + w] + sb[m1 * 9 + w]) * 0.125f + sbias[m1];
        if (!smask[m0]) v0 = -INFINITY;
        if (!smask[m1]) v1 = -INFINITY;
        float mx = fmaxf(v0, v1);
#pragma unroll
        for (int o = 16; o; o >>= 1) mx = fmaxf(mx, __shfl_xor_sync(0xffffffffu, mx, o));
        float e0 = __expf(v0 - mx);
        float e1 = __expf(v1 - mx);
        float s = e0 + e1;
#pragma unroll
        for (int o = 16; o; o >>= 1) s += __shfl_xor_sync(0xffffffffu, s, o);
        float inv = 1.0f / s;
        __half h0 = __float2half_rn(e0 * inv);
        __half h1 = __float2half_rn(e1 * inv);
        uint16_t* ah = (uint16_t*)(sm + AC_AH);
        ah[m0 * 24 + w] = *(uint16_t*)&h0;
        ah[m1 * 24 + w] = *(uint16_t*)&h1;
    }
    __syncthreads();

    {
        float d0[4] = {0.f, 0.f, 0.f, 0.f};
        float d1[4] = {0.f, 0.f, 0.f, 0.f};
        const int c0 = wid * 32;
        const uint32_t bt_base = smb + AC_AH +
            (uint32_t)((((lane >> 3) & 1) * 8 + (lane & 7)) * 48);
        const uint32_t at_row = (uint32_t)(((lane >> 4) & 1) * 8 + (lane & 7));
        const uint32_t at_col = (uint32_t)(((lane >> 3) & 1) * 16);
#pragma unroll
        for (int kk = 0; kk < 4; kk++) {
            uint32_t bh[2];
            ldm_x2_t(bh, bt_base + kk * 16 * 48);
            const uint32_t arow = smb + AC_CH + (kk * 16 + at_row) * AC_LDC + at_col;
            uint32_t ah0[4], ah1[4];
            ldm_x4_t(ah0, arow + c0 * 2);
            ldm_x4_t(ah1, arow + (c0 + 16) * 2);
            mma_f16(d0, ah0, bh);
            mma_f16(d1, ah1, bh);
        }
        const int gg = lane >> 2, tq = lane & 3;
        __half* o = g_ctxAh + (size_t)r * (NHEADS * DC);
        int c = c0 + gg;
        o[(2 * tq) * DC + c]         = __float2half_rn(d0[0]);
        o[(2 * tq + 1) * DC + c]     = __float2half_rn(d0[1]);
        o[(2 * tq) * DC + c + 8]     = __float2half_rn(d0[2]);
        o[(2 * tq + 1) * DC + c + 8] = __float2half_rn(d0[3]);
        c = c0 + 16 + gg;
        o[(2 * tq) * DC + c]         = __float2half_rn(d1[0]);
        o[(2 * tq + 1) * DC + c]     = __float2half_rn(d1[1]);
        o[(2 * tq) * DC + c + 8]     = __float2half_rn(d1[2]);
        o[(2 * tq + 1) * DC + c + 8] = __float2half_rn(d1[3]);
    }
}

// ---------------------------------------------------------------------------
extern "C" void kernel_launch(void* const* d_in, const int* in_sizes, int n_in,
                              void* d_out, int out_size)
{
    const float* x    = (const float*)d_in[0];
    const float* ctx  = (const float*)d_in[1];
    const int*   mask = (const int*)d_in[2];
    const float* bias = (const float*)d_in[3];
    const float* Wq   = (const float*)d_in[4];
    const float* Wk   = (const float*)d_in[5];
    const float* Wv   = (const float*)d_in[6];
    const float* Wo   = (const float*)d_in[7];
    const float* bo   = (const float*)d_in[8];
    float*       out  = (float*)d_out;

    __half *Qhp, *Qkhp, *cAhp, *O1hp;
    cudaGetSymbolAddress((void**)&Qhp,  g_Qh);
    cudaGetSymbolAddress((void**)&Qkhp, g_Qkh);
    cudaGetSymbolAddress((void**)&cAhp, g_ctxAh);
    cudaGetSymbolAddress((void**)&O1hp, g_O1h);

    // smem per variant: 2 * (BM*80 + B_BYTES)
    const int SM_K1 = 2 * (64 * LROWB + 32 * (128 * 2 + 16));   // 27648  (BMODE2, BN=128)
    const int SM_K2 = 2 * (64 * LROWB + 128 * LROWB);           // 30720  (BMODE1, BN=128)
    const int SM_K4 = 2 * (64 * LROWB + 32 * (64 * 2 + 16));    // 19456  (BMODE2, BN=64)

    cudaFuncSetAttribute((const void*)hgemm<64, 128, 2, 4, false, true,  false, 2>,
                         cudaFuncAttributeMaxDynamicSharedMemorySize, SM_K1);
    cudaFuncSetAttribute((const void*)hgemm<64, 128, 2, 4, false, true,  true,  1>,
                         cudaFuncAttributeMaxDynamicSharedMemorySize, SM_K2);
    cudaFuncSetAttribute((const void*)hgemm<64, 64, 2, 4, false, true,  true,  2>,
                         cudaFuncAttributeMaxDynamicSharedMemorySize, SM_K4);
    cudaFuncSetAttribute((const void*)hgemm<64, 128, 2, 4, true,  false, true,  2>,
                         cudaFuncAttributeMaxDynamicSharedMemorySize, SM_K1);
    cudaFuncSetAttribute((const void*)attn_core,
                         cudaFuncAttributeMaxDynamicSharedMemorySize, AC_BYTES);

    // K1: Q = x @ Wq          A: fp32 x [r][512]; B: Wq fp32 [k=512][n=512] trans
    hgemm<64, 128, 2, 4, false, true, false, 2><<<dim3(INNER / 128, R_TOTAL / 64, 1), 256, SM_K1>>>(
        x, DQ, 0, Wq, INNER, 0, Qhp, INNER, 0, nullptr, DQ);

    // K2: Qk = Qh @ Wk^T      A: fp16 Qh (+h*64); B: Wk fp32 [n=c][k] (+h*64 in k)
    hgemm<64, 128, 2, 4, false, true, true, 1><<<dim3(DC / 128, R_TOTAL / 64, NHEADS), 256, SM_K2>>>(
        Qhp, INNER, DHEAD, Wk, INNER, DHEAD, Qkhp, NHEADS * DC, DC, nullptr, DHEAD);

    // K3: fused attention core -> fp16 ctxA
    attn_core<<<R_TOTAL, 256, AC_BYTES>>>(ctx, mask, bias);

    // K4: O1 = ctxAh @ Wv     A: fp16 ctxAh (+h*256); B: Wv fp32 [k=c][n] (+h*64 in n) trans
    hgemm<64, 64, 2, 4, false, true, true, 2><<<dim3(1, R_TOTAL / 64, NHEADS), 256, SM_K4>>>(
        cAhp, NHEADS * DC, DC, Wv, INNER, DHEAD, O1hp, INNER, DHEAD, nullptr, DC);

    // K5: out = O1h @ Wo + bo A: fp16 O1h; B: Wo fp32 [k=512][n=512] trans
    hgemm<64, 128, 2, 4, true, false, true, 2><<<dim3(DQ / 128, R_TOTAL / 64, 1), 256, SM_K1>>>(
        O1hp, INNER, 0, Wo, DQ, 0, out, DQ, 0, bo, INNER);
}

// round 17
// speedup vs baseline: 1.1634x; 1.1000x over previous
#include <cuda_runtime.h>
#include <cuda_fp16.h>
#include <math.h>
#include <stdint.h>

// Shapes (fixed)
#define R_TOTAL 4096
#define DQ      512
#define DC      256
#define MTOK    64
#define NHEADS  8
#define DHEAD   64
#define INNER   512

// Scratch (no allocs allowed)
__device__ __half g_xh   [R_TOTAL * DQ];             // 4 MB
__device__ __half g_Qh   [R_TOTAL * INNER];          // 4 MB
__device__ __half g_Qkh  [R_TOTAL * NHEADS * DC];    // 16 MB
__device__ __half g_ctxAh[R_TOTAL * NHEADS * DC];    // 16 MB
__device__ __half g_O1h  [R_TOTAL * INNER];          // 4 MB
__device__ __half g_Wqh  [DQ * INNER];               // [k][n]
__device__ __half g_Wkh  [DC * INNER];               // [n][k]
__device__ __half g_Wvh  [DC * INNER];               // [k][n]
__device__ __half g_Woh  [INNER * DQ];               // [k][n]

// ---------------- helpers ----------------
__device__ __forceinline__ uint32_t smem_u32(const void* p) {
    uint32_t a;
    asm("{ .reg .u64 t; cvta.to.shared.u64 t, %1; cvt.u32.u64 %0, t; }"
        : "=r"(a) : "l"(p));
    return a;
}
__device__ __forceinline__ void ldm_x4(uint32_t* r, uint32_t addr) {
    asm volatile("ldmatrix.sync.aligned.m8n8.x4.shared.b16 {%0,%1,%2,%3}, [%4];"
                 : "=r"(r[0]), "=r"(r[1]), "=r"(r[2]), "=r"(r[3]) : "r"(addr));
}
__device__ __forceinline__ void ldm_x2(uint32_t* r, uint32_t addr) {
    asm volatile("ldmatrix.sync.aligned.m8n8.x2.shared.b16 {%0,%1}, [%2];"
                 : "=r"(r[0]), "=r"(r[1]) : "r"(addr));
}
__device__ __forceinline__ void ldm_x4_t(uint32_t* r, uint32_t addr) {
    asm volatile("ldmatrix.sync.aligned.m8n8.x4.trans.shared.b16 {%0,%1,%2,%3}, [%4];"
                 : "=r"(r[0]), "=r"(r[1]), "=r"(r[2]), "=r"(r[3]) : "r"(addr));
}
__device__ __forceinline__ void ldm_x2_t(uint32_t* r, uint32_t addr) {
    asm volatile("ldmatrix.sync.aligned.m8n8.x2.trans.shared.b16 {%0,%1}, [%2];"
                 : "=r"(r[0]), "=r"(r[1]) : "r"(addr));
}
__device__ __forceinline__ void mma_f16(float* c, const uint32_t* a, const uint32_t* b) {
    asm volatile("mma.sync.aligned.m16n8k16.row.col.f32.f16.f16.f32 "
                 "{%0,%1,%2,%3}, {%4,%5,%6,%7}, {%8,%9}, {%0,%1,%2,%3};"
                 : "+f"(c[0]), "+f"(c[1]), "+f"(c[2]), "+f"(c[3])
                 : "r"(a[0]), "r"(a[1]), "r"(a[2]), "r"(a[3]), "r"(b[0]), "r"(b[1]));
}
__device__ __forceinline__ uint2 pack_h(float4 v) {
    __half2 h01 = __float22half2_rn(make_float2(v.x, v.y));
    __half2 h23 = __float22half2_rn(make_float2(v.z, v.w));
    return make_uint2(*(uint32_t*)&h01, *(uint32_t*)&h23);
}
__device__ __forceinline__ void cp16(uint32_t dst, const void* src) {
    asm volatile("cp.async.cg.shared.global [%0], [%1], 16;"
                 :: "r"(dst), "l"(src) : "memory");
}
#define CP_COMMIT() asm volatile("cp.async.commit_group;" ::: "memory")
#define CP_WAIT1()  asm volatile("cp.async.wait_group 1;" ::: "memory")
#define CP_WAIT0()  asm volatile("cp.async.wait_group 0;" ::: "memory")

// ---------------------------------------------------------------------------
// One-shot fp16 prepack of x + all weights (layouts preserved).
// Rounding identical to previous per-tile pack_h => bit-identical results.
// ---------------------------------------------------------------------------
#define X4  524288                    // x float4 count
#define B1  589824                    // + Wq (65536)
#define B2  622592                    // + Wk (32768)
#define B3  655360                    // + Wv (32768)
#define TOT 720896                    // + Wo (65536)

__global__ void pack_all(const float* __restrict__ x,  const float* __restrict__ Wq,
                         const float* __restrict__ Wk, const float* __restrict__ Wv,
                         const float* __restrict__ Wo)
{
    int i = blockIdx.x * 256 + threadIdx.x;
    const float* s; __half* d; int off;
    if (i < X4)      { s = x;  d = g_xh;  off = i; }
    else if (i < B1) { s = Wq; d = g_Wqh; off = i - X4; }
    else if (i < B2) { s = Wk; d = g_Wkh; off = i - B1; }
    else if (i < B3) { s = Wv; d = g_Wvh; off = i - B2; }
    else             { s = Wo; d = g_Woh; off = i - B3; }
    float4 v = ((const float4*)s)[off];
    *(uint2*)(d + (size_t)off * 4) = pack_h(v);
}

// ---------------------------------------------------------------------------
// All-fp16 GEMM, cp.async 3-stage pipeline.
// A fp16 [m][k]. BMODE1: B fp16 [n][k]; BMODE2: B fp16 [k][n] (ldmatrix.trans)
// ---------------------------------------------------------------------------
#define LROW 40
#define LROWB 80

template<int BN, bool BIAS, bool HOUT, int BMODE>
__global__ __launch_bounds__(256, 3)
void hgemm(const __half* __restrict__ A, int lda, long long bsA,
           const __half* __restrict__ B, int ldb, long long bsB,
           void* __restrict__ Cv, int ldc, long long bsC,
           const float* __restrict__ bias, int K)
{
    constexpr int BM = 64, MW = 2, NW = 4;
    constexpr int WM = BM / MW;                  // 32
    constexpr int WN = BN / NW;
    constexpr int MT = WM / 16;                  // 2
    constexpr int NT = WN / 8;
    constexpr int A_BYTES = BM * LROWB;          // 5120
    constexpr int BROWB   = (BMODE == 2) ? (BN * 2 + 16) : LROWB;
    constexpr int B_BYTES = (BMODE == 2) ? (32 * BROWB) : (BN * LROWB);
    constexpr int STAGE = A_BYTES + B_BYTES;

    extern __shared__ char smc[];
    const uint32_t smb = smem_u32(smc);

    const int t = threadIdx.x;
    const int wid = t >> 5, lane = t & 31;
    const int wr = wid / NW, wc = wid % NW;
    const int wm = wr * WM, wn = wc * WN;
    const int bm = blockIdx.y * BM, bn = blockIdx.x * BN;

    A += (long long)blockIdx.z * bsA;
    B += (long long)blockIdx.z * bsB;

    float acc[MT][NT][4];
#pragma unroll
    for (int i = 0; i < MT; i++)
#pragma unroll
        for (int j = 0; j < NT; j++)
#pragma unroll
            for (int q = 0; q < 4; q++) acc[i][j][q] = 0.0f;

    const int ns = K >> 5;

    const uint32_t a_off  = (uint32_t)(((wm + (lane & 15)) * LROW + (lane >> 4) * 8) * 2);
    const uint32_t b_off1 = (uint32_t)(((wn + (lane & 7)) * LROW + ((lane >> 3) & 1) * 8) * 2);
    const uint32_t b_off2 = (uint32_t)(((((lane >> 3) & 1) * 8 + (lane & 7)) * BROWB) + wn * 2);

    auto issue = [&](int s) {
        const uint32_t base = smb + (s % 3) * STAGE;
        // A: 64 rows x 64B; thread -> (row=t>>2, chunk=t&3)
        {
            int row = t >> 2, ch = t & 3;
            cp16(base + row * LROWB + ch * 16,
                 A + (long long)(bm + row) * lda + s * 32 + ch * 8);
        }
        const uint32_t bb = base + A_BYTES;
        if (BMODE == 1) {
            // BN rows x 64B
#pragma unroll
            for (int i = 0; i < BN / 64; i++) {
                int row = (t >> 2) + i * 64, ch = t & 3;
                cp16(bb + row * LROWB + ch * 16,
                     B + (long long)(bn + row) * ldb + s * 32 + ch * 8);
            }
        } else {
            // 32 k-rows x BN*2 bytes
            constexpr int CPR = BN / 8;          // 16B chunks per row
            constexpr int RPI = 256 / CPR;       // rows per iteration
#pragma unroll
            for (int i = 0; i < 32 / RPI; i++) {
                int row = t / CPR + i * RPI, ch = t % CPR;
                cp16(bb + row * BROWB + ch * 16,
                     B + (long long)(s * 32 + row) * ldb + bn + ch * 8);
            }
        }
    };
    auto compute = [&](int s) {
        const uint32_t sa = smb + (s % 3) * STAGE;
        const uint32_t sb = sa + A_BYTES;
#pragma unroll
        for (int ks = 0; ks < 2; ks++) {
            uint32_t afh[MT][4], bfh[NT][2];
#pragma unroll
            for (int mt = 0; mt < MT; mt++)
                ldm_x4(afh[mt], sa + a_off + mt * (16 * LROWB) + ks * 32);
#pragma unroll
            for (int nt = 0; nt < NT; nt++) {
                if (BMODE == 1)
                    ldm_x2(bfh[nt], sb + b_off1 + nt * (8 * LROWB) + ks * 32);
                else
                    ldm_x2_t(bfh[nt], sb + b_off2 + nt * 16 + ks * (16 * BROWB));
            }
#pragma unroll
            for (int mt = 0; mt < MT; mt++)
#pragma unroll
                for (int nt = 0; nt < NT; nt++)
                    mma_f16(acc[mt][nt], afh[mt], bfh[nt]);
        }
    };

    issue(0); CP_COMMIT();
    if (ns > 1) { issue(1); CP_COMMIT(); }
    for (int s = 0; s < ns; s++) {
        if (s + 2 < ns) CP_WAIT1(); else CP_WAIT0();
        __syncthreads();
        compute(s);
        if (s + 2 < ns) { issue(s + 2); CP_COMMIT(); }
    }

    const int g = lane >> 2, tq = lane & 3;
    if (HOUT) {
        __half* C = (__half*)Cv + (long long)blockIdx.z * bsC;
#pragma unroll
        for (int mt = 0; mt < MT; mt++) {
            int r0 = bm + wm + mt * 16 + g;
#pragma unroll
            for (int nt = 0; nt < NT; nt++) {
                int col = bn + wn + nt * 8 + tq * 2;
                __half2 v0 = __float22half2_rn(make_float2(acc[mt][nt][0], acc[mt][nt][1]));
                __half2 v1 = __float22half2_rn(make_float2(acc[mt][nt][2], acc[mt][nt][3]));
                *(__half2*)(C + (long long)r0 * ldc + col)       = v0;
                *(__half2*)(C + (long long)(r0 + 8) * ldc + col) = v1;
            }
        }
    } else {
        float* C = (float*)Cv + (long long)blockIdx.z * bsC;
#pragma unroll
        for (int mt = 0; mt < MT; mt++) {
            int r0 = bm + wm + mt * 16 + g;
#pragma unroll
            for (int nt = 0; nt < NT; nt++) {
                int col = bn + wn + nt * 8 + tq * 2;
                float b0 = 0.f, b1 = 0.f;
                if (BIAS) { b0 = bias[col]; b1 = bias[col + 1]; }
                *(float2*)(C + (long long)r0 * ldc + col) =
                    make_float2(acc[mt][nt][0] + b0, acc[mt][nt][1] + b1);
                *(float2*)(C + (long long)(r0 + 8) * ldc + col) =
                    make_float2(acc[mt][nt][2] + b0, acc[mt][nt][3] + b1);
            }
        }
    }
}

// ---------------------------------------------------------------------------
// Tensor-core attention core, single-term fp16 (unchanged, proven).
// ---------------------------------------------------------------------------
#define AC_LDC 528
#define AC_CH 0
#define AC_QH 33792
#define AC_AH 38016
#define AC_SA 41088
#define AC_SB 43392
#define AC_BI 45696
#define AC_MK 45952
#define AC_BYTES 46208

__global__ __launch_bounds__(256)
void attn_core(const float* __restrict__ ctx,
               const int* __restrict__ mask,
               const float* __restrict__ bias)
{
    extern __shared__ char sm[];
    const uint32_t smb = smem_u32(sm);
    const int r = blockIdx.x, t = threadIdx.x;
    const int wid = t >> 5, lane = t & 31;

    {
        const float4* g = (const float4*)(ctx + (size_t)r * (MTOK * DC));
#pragma unroll
        for (int s = 0; s < 16; s++) {
            int i = t + s * 256;
            int m = i >> 6, c4 = i & 63;
            *(uint2*)(sm + AC_CH + m * AC_LDC + c4 * 8) = pack_h(g[i]);
        }
        {
            const uint4* gq = (const uint4*)(g_Qkh + (size_t)r * (NHEADS * DC));
            uint4 v = gq[t];
            int h = t >> 5, c16 = t & 31;
            *(uint4*)(sm + AC_QH + h * AC_LDC + c16 * 16) = v;
        }
        if (t < MTOK) {
            ((float*)(sm + AC_BI))[t] = bias[(size_t)r * MTOK + t];
            ((int*)(sm + AC_MK))[t]   = mask[(size_t)r * MTOK + t];
        }
    }
    __syncthreads();

    {
        const int mtile = wid & 3, khalf = wid >> 2;
        float d[4] = {0.f, 0.f, 0.f, 0.f};
        const uint32_t a_base = smb + AC_CH +
            (uint32_t)((mtile * 16 + (lane & 15)) * AC_LDC + (lane >> 4) * 16);
        const uint32_t b_base = smb + AC_QH +
            (uint32_t)((lane & 7) * AC_LDC + ((lane >> 3) & 1) * 16);
#pragma unroll
        for (int j = 0; j < 8; j++) {
            const int kk = khalf * 8 + j;
            uint32_t ah[4], bh[2];
            ldm_x4(ah, a_base + kk * 32);
            ldm_x2(bh, b_base + kk * 32);
            mma_f16(d, ah, bh);
        }
        float* ss = (float*)(sm + (khalf ? AC_SB : AC_SA));
        const int gg = lane >> 2, tq = lane & 3;
        const int m0 = mtile * 16 + gg;
        ss[m0 * 9 + 2 * tq]           = d[0];
        ss[m0 * 9 + 2 * tq + 1]       = d[1];
        ss[(m0 + 8) * 9 + 2 * tq]     = d[2];
        ss[(m0 + 8) * 9 + 2 * tq + 1] = d[3];
    }
    __syncthreads();

    {
        const int w = wid;
        const float* sa = (const float*)(sm + AC_SA);
        const float* sb = (const float*)(sm + AC_SB);
        const float* sbias = (const float*)(sm + AC_BI);
        const int*   smask = (const int*)(sm + AC_MK);
        const int m0 = lane, m1 = lane + 32;
        float v0 = (sa[m0 * 9 + w] + sb[m0 * 9 + w]) * 0.125f + sbias[m0];
        float v1 = (sa[m1 * 9 + w] + sb[m1 * 9 + w]) * 0.125f + sbias[m1];
        if (!smask[m0]) v0 = -INFINITY;
        if (!smask[m1]) v1 = -INFINITY;
        float mx = fmaxf(v0, v1);
#pragma unroll
        for (int o = 16; o; o >>= 1) mx = fmaxf(mx, __shfl_xor_sync(0xffffffffu, mx, o));
        float e0 = __expf(v0 - mx);
        float e1 = __expf(v1 - mx);
        float s = e0 + e1;
#pragma unroll
        for (int o = 16; o; o >>= 1) s += __shfl_xor_sync(0xffffffffu, s, o);
        float inv = 1.0f / s;
        __half h0 = __float2half_rn(e0 * inv);
        __half h1 = __float2half_rn(e1 * inv);
        uint16_t* ah = (uint16_t*)(sm + AC_AH);
        ah[m0 * 24 + w] = *(uint16_t*)&h0;
        ah[m1 * 24 + w] = *(uint16_t*)&h1;
    }
    __syncthreads();

    {
        float d0[4] = {0.f, 0.f, 0.f, 0.f};
        float d1[4] = {0.f, 0.f, 0.f, 0.f};
        const int c0 = wid * 32;
        const uint32_t bt_base = smb + AC_AH +
            (uint32_t)((((lane >> 3) & 1) * 8 + (lane & 7)) * 48);
        const uint32_t at_row = (uint32_t)(((lane >> 4) & 1) * 8 + (lane & 7));
        const uint32_t at_col = (uint32_t)(((lane >> 3) & 1) * 16);
#pragma unroll
        for (int kk = 0; kk < 4; kk++) {
            uint32_t bh[2];
            ldm_x2_t(bh, bt_base + kk * 16 * 48);
            const uint32_t arow = smb + AC_CH + (kk * 16 + at_row) * AC_LDC + at_col;
            uint32_t ah0[4], ah1[4];
            ldm_x4_t(ah0, arow + c0 * 2);
            ldm_x4_t(ah1, arow + (c0 + 16) * 2);
            mma_f16(d0, ah0, bh);
            mma_f16(d1, ah1, bh);
        }
        const int gg = lane >> 2, tq = lane & 3;
        __half* o = g_ctxAh + (size_t)r * (NHEADS * DC);
        int c = c0 + gg;
        o[(2 * tq) * DC + c]         = __float2half_rn(d0[0]);
        o[(2 * tq + 1) * DC + c]     = __float2half_rn(d0[1]);
        o[(2 * tq) * DC + c + 8]     = __float2half_rn(d0[2]);
        o[(2 * tq + 1) * DC + c + 8] = __float2half_rn(d0[3]);
        c = c0 + 16 + gg;
        o[(2 * tq) * DC + c]         = __float2half_rn(d1[0]);
        o[(2 * tq + 1) * DC + c]     = __float2half_rn(d1[1]);
        o[(2 * tq) * DC + c + 8]     = __float2half_rn(d1[2]);
        o[(2 * tq + 1) * DC + c + 8] = __float2half_rn(d1[3]);
    }
}

// ---------------------------------------------------------------------------
extern "C" void kernel_launch(void* const* d_in, const int* in_sizes, int n_in,
                              void* d_out, int out_size)
{
    const float* x    = (const float*)d_in[0];
    const float* ctx  = (const float*)d_in[1];
    const int*   mask = (const int*)d_in[2];
    const float* bias = (const float*)d_in[3];
    const float* Wq   = (const float*)d_in[4];
    const float* Wk   = (const float*)d_in[5];
    const float* Wv   = (const float*)d_in[6];
    const float* Wo   = (const float*)d_in[7];
    const float* bo   = (const float*)d_in[8];
    float*       out  = (float*)d_out;

    __half *xhp, *Qhp, *Qkhp, *cAhp, *O1hp, *Wqhp, *Wkhp, *Wvhp, *Wohp;
    cudaGetSymbolAddress((void**)&xhp,  g_xh);
    cudaGetSymbolAddress((void**)&Qhp,  g_Qh);
    cudaGetSymbolAddress((void**)&Qkhp, g_Qkh);
    cudaGetSymbolAddress((void**)&cAhp, g_ctxAh);
    cudaGetSymbolAddress((void**)&O1hp, g_O1h);
    cudaGetSymbolAddress((void**)&Wqhp, g_Wqh);
    cudaGetSymbolAddress((void**)&Wkhp, g_Wkh);
    cudaGetSymbolAddress((void**)&Wvhp, g_Wvh);
    cudaGetSymbolAddress((void**)&Wohp, g_Woh);

    // smem: 3 stages * (5120 + B_BYTES)
    const int SM_B2_128 = 3 * (5120 + 32 * (128 * 2 + 16));   // 41472
    const int SM_B1_128 = 3 * (5120 + 128 * LROWB);           // 46080
    const int SM_B2_64  = 3 * (5120 + 32 * (64 * 2 + 16));    // 29184

    cudaFuncSetAttribute((const void*)hgemm<128, false, true,  2>,
                         cudaFuncAttributeMaxDynamicSharedMemorySize, SM_B2_128);
    cudaFuncSetAttribute((const void*)hgemm<128, false, true,  1>,
                         cudaFuncAttributeMaxDynamicSharedMemorySize, SM_B1_128);
    cudaFuncSetAttribute((const void*)hgemm<64,  false, true,  2>,
                         cudaFuncAttributeMaxDynamicSharedMemorySize, SM_B2_64);
    cudaFuncSetAttribute((const void*)hgemm<128, true,  false, 2>,
                         cudaFuncAttributeMaxDynamicSharedMemorySize, SM_B2_128);
    cudaFuncSetAttribute((const void*)attn_core,
                         cudaFuncAttributeMaxDynamicSharedMemorySize, AC_BYTES);

    // P0: fp16 prepack of x + weights (one launch)
    pack_all<<<TOT / 256, 256>>>(x, Wq, Wk, Wv, Wo);

    // K1: Q = xh @ Wqh    B: [k=512][n=512] trans
    hgemm<128, false, true, 2><<<dim3(INNER / 128, R_TOTAL / 64, 1), 256, SM_B2_128>>>(
        xhp, DQ, 0, Wqhp, INNER, 0, Qhp, INNER, 0, nullptr, DQ);

    // K2: Qk = Qh @ Wkh^T (per head)   B: [n][k], k-offset h*64
    hgemm<128, false, true, 1><<<dim3(DC / 128, R_TOTAL / 64, NHEADS), 256, SM_B1_128>>>(
        Qhp, INNER, DHEAD, Wkhp, INNER, DHEAD, Qkhp, NHEADS * DC, DC, nullptr, DHEAD);

    // K3: fused attention core -> fp16 ctxA
    attn_core<<<R_TOTAL, 256, AC_BYTES>>>(ctx, mask, bias);

    // K4: O1 = ctxAh @ Wvh (per head)  B: [k=c][n], n-offset h*64, trans
    hgemm<64, false, true, 2><<<dim3(1, R_TOTAL / 64, NHEADS), 256, SM_B2_64>>>(
        cAhp, NHEADS * DC, DC, Wvhp, INNER, DHEAD, O1hp, INNER, DHEAD, nullptr, DC);

    // K5: out = O1h @ Woh + bo   B: [k=512][n=512] trans, fp32 out
    hgemm<128, true, false, 2><<<dim3(DQ / 128, R_TOTAL / 64, 1), 256, SM_B2_128>>>(
        O1hp, INNER, 0, Wohp, DQ, 0, out, DQ, 0, bo, INNER);
}